// round 9
// baseline (speedup 1.0000x reference)
#include <cuda_runtime.h>

#define IN_DIM 128
#define HD     128
#define MAXN   40000
#define MAXE   640000

typedef unsigned long long u64;

// Scratch (allocation-free: __device__ globals)
__device__ float g_Q[MAXN * HD];
__device__ float g_K[MAXN * HD];
__device__ float g_V[MAXN * HD];
__device__ int   g_cnt[MAXN];
__device__ int   g_rowptr[MAXN + 1];
__device__ int   g_cursor[MAXN];
__device__ int   g_eidx[MAXE];   // edge indices grouped by dst
__device__ int   g_srcs[MAXE];   // src[eidx] in ascending-edge order per dst

// Packed dual-FP32 FMA (Blackwell f32x2 pipe). Each half is an independent
// IEEE fp32 fma.rn — bit-identical to two scalar __fmaf_rn.
__device__ __forceinline__ u64 fma2(u64 a, u64 b, u64 c)
{
    u64 d;
    asm("fma.rn.f32x2 %0, %1, %2, %3;" : "=l"(d) : "l"(a), "l"(b), "l"(c));
    return d;
}
__device__ __forceinline__ u64 dup2(float x)
{
    u64 d;
    asm("mov.b64 %0, {%1, %1};" : "=l"(d) : "f"(x));
    return d;
}

// ---------------------------------------------------------------------------
// CSR build: histogram by dst
// ---------------------------------------------------------------------------
__global__ void histogram_kernel(const int* __restrict__ dst, int E)
{
    int e = blockIdx.x * blockDim.x + threadIdx.x;
    if (e < E) atomicAdd(&g_cnt[dst[e]], 1);
}

// Single-block exclusive scan over g_cnt -> g_rowptr / g_cursor
__global__ void scan_kernel(int n)
{
    __shared__ int sm[1024];
    const int t = threadIdx.x;
    const int chunk = (n + 1023) / 1024;
    int b = t * chunk;
    int e = b + chunk; if (e > n) e = n;
    if (b > n) b = n;

    int s = 0;
    for (int i = b; i < e; i++) s += g_cnt[i];
    sm[t] = s;
    __syncthreads();
    for (int off = 1; off < 1024; off <<= 1) {
        int x = (t >= off) ? sm[t - off] : 0;
        __syncthreads();
        sm[t] += x;
        __syncthreads();
    }
    int run = sm[t] - s;
    for (int i = b; i < e; i++) {
        g_rowptr[i] = run;
        g_cursor[i] = run;
        run += g_cnt[i];
    }
    if (t == 1023) g_rowptr[n] = sm[1023];
}

// Scatter EDGE INDICES (intra-row order arbitrary; fixed by rank sort below)
__global__ void scatter_kernel(const int* __restrict__ dst, int E)
{
    int e = blockIdx.x * blockDim.x + threadIdx.x;
    if (e < E) {
        int d = dst[e];
        int pos = atomicAdd(&g_cursor[d], 1);
        g_eidx[pos] = e;
    }
}

// Warp-per-node rank sort. Edge indices are distinct: ascending position of
// x is |{y : y < x}|. d<=32: pure register/shfl path (no smem, no syncwarp).
__global__ __launch_bounds__(256) void sortwarp_kernel(const int* __restrict__ src, int n)
{
    __shared__ int buf[8][128];
    const int warp   = (blockIdx.x * blockDim.x + threadIdx.x) >> 5;
    const int wlocal = (threadIdx.x >> 5);
    const int lane   = threadIdx.x & 31;
    if (warp >= n) return;

    const int beg = g_rowptr[warp];
    const int end = g_rowptr[warp + 1];
    const int d   = end - beg;

    if (d <= 0) return;
    if (d == 1) {
        if (lane == 0) g_srcs[beg] = src[g_eidx[beg]];
        return;
    }
    if (d <= 32) {
        int e = (lane < d) ? g_eidx[beg + lane] : 0x7fffffff;
        int r = 0;
#pragma unroll
        for (int j = 0; j < 32; j++) {
            int x = __shfl_sync(0xffffffffu, e, j);
            r += (x < e);
        }
        if (lane < d) g_srcs[beg + r] = src[e];
        return;
    }
    if (d <= 128) {
        for (int i = lane; i < d; i += 32) buf[wlocal][i] = g_eidx[beg + i];
        __syncwarp();
        for (int i = lane; i < d; i += 32) {
            int e = buf[wlocal][i];
            int r = 0;
            for (int j = 0; j < d; j++) r += (buf[wlocal][j] < e);
            g_srcs[beg + r] = src[e];
        }
    } else if (lane == 0) {  // astronomically unlikely fallback
        for (int i = beg + 1; i < end; i++) {
            int key = g_eidx[i];
            int j = i - 1;
            while (j >= beg && g_eidx[j] > key) { g_eidx[j + 1] = g_eidx[j]; j--; }
            g_eidx[j + 1] = key;
        }
        for (int i = beg; i < end; i++) g_srcs[i] = src[g_eidx[i]];
    }
}

// ---------------------------------------------------------------------------
// QKV GEMM (fp32) v3: C = A[M x 128] * W[128 x 128] (blockIdx.y: 0=Q,1=K,2=V)
// Per output element: one sequential fused-FMA chain over k = 0..127
// ascending (bit-exact vs reference), packed fma.rn.f32x2 over column pairs.
// v3: A stored in smem as duplicated pairs (a,a) so the inner loop loads the
// packed broadcast operand directly (no dup movs), and smem is double-
// buffered (one __syncthreads per chunk; loads overlap compute).
// 128x128 block tile, BK=8, 256 threads, 8 rows x 8 cols per thread.
// ---------------------------------------------------------------------------
__global__ __launch_bounds__(256) void qkv_gemm(
    const float* __restrict__ A,
    const float* __restrict__ WQ,
    const float* __restrict__ WK,
    const float* __restrict__ WV,
    int M)
{
    const float* W = (blockIdx.y == 0) ? WQ : (blockIdx.y == 1) ? WK : WV;
    float* C = (blockIdx.y == 0) ? g_Q : (blockIdx.y == 1) ? g_K : g_V;

    __shared__ float As2[2][8][256];  // [buf][k][2m] duplicated pairs, 16 KB
    __shared__ float Bs[2][8][128];   // [buf][k][n],                    8 KB

    const int tid  = threadIdx.x;
    const int row0 = blockIdx.x * 128;

    const int tr = (tid >> 4) * 8;
    const int tc = (tid & 15) * 8;

    const int arow  = tid >> 1;          // 0..127
    const int akcol = (tid & 1) * 4;     // 0 or 4
    const int brow  = tid >> 5;          // 0..7
    const int bcol  = (tid & 31) * 4;    // 0..124

    const bool arow_ok = (row0 + arow < M);

    // acc2[i][p] = packed (C[tr+i][tc+2p], C[tr+i][tc+2p+1])
    u64 acc2[8][4];
#pragma unroll
    for (int i = 0; i < 8; i++)
#pragma unroll
        for (int p = 0; p < 4; p++) acc2[i][p] = 0ULL;

    // chunk loader: global -> smem buffer b for k-range [c*8, c*8+8)
    auto load_chunk = [&](int c, int b) {
        float4 av = make_float4(0.f, 0.f, 0.f, 0.f);
        if (arow_ok)
            av = *(const float4*)&A[(row0 + arow) * IN_DIM + c * 8 + akcol];
        *(u64*)&As2[b][akcol + 0][2 * arow] = dup2(av.x);
        *(u64*)&As2[b][akcol + 1][2 * arow] = dup2(av.y);
        *(u64*)&As2[b][akcol + 2][2 * arow] = dup2(av.z);
        *(u64*)&As2[b][akcol + 3][2 * arow] = dup2(av.w);
        *(float4*)&Bs[b][brow][bcol] =
            *(const float4*)&W[(c * 8 + brow) * HD + bcol];
    };

    load_chunk(0, 0);
    __syncthreads();

    for (int c = 0; c < IN_DIM / 8; c++) {
        const int pb = c & 1;
        if (c + 1 < IN_DIM / 8) load_chunk(c + 1, pb ^ 1);

#pragma unroll
        for (int k = 0; k < 8; k++) {
            // packed broadcast a-pairs for rows tr..tr+7 (4 x 16B loads)
            ulonglong2 a01 = *(const ulonglong2*)&As2[pb][k][2 * tr];
            ulonglong2 a23 = *(const ulonglong2*)&As2[pb][k][2 * tr + 4];
            ulonglong2 a45 = *(const ulonglong2*)&As2[pb][k][2 * tr + 8];
            ulonglong2 a67 = *(const ulonglong2*)&As2[pb][k][2 * tr + 12];
            ulonglong2 bl  = *(const ulonglong2*)&Bs[pb][k][tc];
            ulonglong2 bh  = *(const ulonglong2*)&Bs[pb][k][tc + 4];
            u64 a[8] = { a01.x, a01.y, a23.x, a23.y, a45.x, a45.y, a67.x, a67.y };
#pragma unroll
            for (int i = 0; i < 8; i++) {
                acc2[i][0] = fma2(a[i], bl.x, acc2[i][0]);
                acc2[i][1] = fma2(a[i], bl.y, acc2[i][1]);
                acc2[i][2] = fma2(a[i], bh.x, acc2[i][2]);
                acc2[i][3] = fma2(a[i], bh.y, acc2[i][3]);
            }
        }
        __syncthreads();
    }

#pragma unroll
    for (int i = 0; i < 8; i++) {
        int r = row0 + tr + i;
        if (r < M) {
            *(ulonglong2*)&C[r * HD + tc]     = make_ulonglong2(acc2[i][0], acc2[i][1]);
            *(ulonglong2*)&C[r * HD + tc + 4] = make_ulonglong2(acc2[i][2], acc2[i][3]);
        }
    }
}

// ---------------------------------------------------------------------------
// Edge phase (measured-good R6/R8 version, unroll x4):
//   score = (K[src]*Q[dst]) * 0.25f ; z += score ; wv += V[src]*score
//   out   = wv / (z + 1e-6f)        all in ascending edge order, bit-exact.
// At its compulsory L2-traffic floor (~655 MB); do not touch.
// ---------------------------------------------------------------------------
__device__ __forceinline__ void edge_step(float4 k, float4 v, const float4& q,
                                          float4& z, float4& w)
{
    float sc0 = __fmul_rn(__fmul_rn(k.x, q.x), 0.25f);
    float sc1 = __fmul_rn(__fmul_rn(k.y, q.y), 0.25f);
    float sc2 = __fmul_rn(__fmul_rn(k.z, q.z), 0.25f);
    float sc3 = __fmul_rn(__fmul_rn(k.w, q.w), 0.25f);
    z.x = __fadd_rn(z.x, sc0);
    z.y = __fadd_rn(z.y, sc1);
    z.z = __fadd_rn(z.z, sc2);
    z.w = __fadd_rn(z.w, sc3);
    w.x = __fadd_rn(w.x, __fmul_rn(v.x, sc0));
    w.y = __fadd_rn(w.y, __fmul_rn(v.y, sc1));
    w.z = __fadd_rn(w.z, __fmul_rn(v.z, sc2));
    w.w = __fadd_rn(w.w, __fmul_rn(v.w, sc3));
}

__global__ __launch_bounds__(256) void aggregate_kernel(float* __restrict__ out, int n)
{
    int node = (blockIdx.x * blockDim.x + threadIdx.x) >> 5;
    if (node >= n) return;
    const int lane = threadIdx.x & 31;

    const int beg = g_rowptr[node];
    const int end = g_rowptr[node + 1];

    const float4* __restrict__ K4 = (const float4*)g_K;
    const float4* __restrict__ V4 = (const float4*)g_V;

    float4 q = ((const float4*)g_Q)[node * 32 + lane];

    float4 z = make_float4(0.f, 0.f, 0.f, 0.f);
    float4 w = make_float4(0.f, 0.f, 0.f, 0.f);

    int j = beg;
    for (; j + 4 <= end; j += 4) {
        int s0 = g_srcs[j + 0];
        int s1 = g_srcs[j + 1];
        int s2 = g_srcs[j + 2];
        int s3 = g_srcs[j + 3];
        float4 k0 = K4[s0 * 32 + lane], v0 = V4[s0 * 32 + lane];
        float4 k1 = K4[s1 * 32 + lane], v1 = V4[s1 * 32 + lane];
        float4 k2 = K4[s2 * 32 + lane], v2 = V4[s2 * 32 + lane];
        float4 k3 = K4[s3 * 32 + lane], v3 = V4[s3 * 32 + lane];
        edge_step(k0, v0, q, z, w);
        edge_step(k1, v1, q, z, w);
        edge_step(k2, v2, q, z, w);
        edge_step(k3, v3, q, z, w);
    }
    for (; j < end; j++) {
        int s = g_srcs[j];
        edge_step(K4[s * 32 + lane], V4[s * 32 + lane], q, z, w);
    }

    float4 r;
    r.x = __fdiv_rn(w.x, __fadd_rn(z.x, 1e-6f));
    r.y = __fdiv_rn(w.y, __fadd_rn(z.y, 1e-6f));
    r.z = __fdiv_rn(w.z, __fadd_rn(z.z, 1e-6f));
    r.w = __fdiv_rn(w.w, __fadd_rn(z.w, 1e-6f));

    ((float4*)out)[node * 32 + lane] = r;
}

// ---------------------------------------------------------------------------
// Launch: fork the (independent) QKV GEMM onto a second capture stream so the
// CSR-build chain overlaps it in the captured graph; join before aggregate.
// Streams/events are host objects (no device memory) created fresh per call.
// ---------------------------------------------------------------------------
extern "C" void kernel_launch(void* const* d_in, const int* in_sizes, int n_in,
                              void* d_out, int out_size)
{
    const float* h   = (const float*)d_in[0];
    const int*   src = (const int*)  d_in[1];
    const int*   dst = (const int*)  d_in[2];
    const float* WQ  = (const float*)d_in[3];
    const float* WK  = (const float*)d_in[4];
    const float* WV  = (const float*)d_in[5];
    float* out = (float*)d_out;

    const int N = in_sizes[0] / IN_DIM;
    const int E = in_sizes[1];

    // Try to set up a parallel branch for the GEMM
    cudaStream_t s2 = nullptr;
    cudaEvent_t evFork = nullptr, evJoin = nullptr;
    bool forked =
        (cudaStreamCreateWithFlags(&s2, cudaStreamNonBlocking) == cudaSuccess) &&
        (cudaEventCreateWithFlags(&evFork, cudaEventDisableTiming) == cudaSuccess) &&
        (cudaEventCreateWithFlags(&evJoin, cudaEventDisableTiming) == cudaSuccess);

    dim3 ggrid((N + 127) / 128, 3);

    if (forked) {
        forked = (cudaEventRecord(evFork, 0) == cudaSuccess) &&
                 (cudaStreamWaitEvent(s2, evFork, 0) == cudaSuccess);
    }
    if (forked) {
        qkv_gemm<<<ggrid, 256, 0, s2>>>(h, WQ, WK, WV, N);
        forked = (cudaEventRecord(evJoin, s2) == cudaSuccess);
    }

    // CSR-build chain on the main (captured) stream
    void* cntPtr = nullptr;
    cudaGetSymbolAddress(&cntPtr, g_cnt);
    cudaMemsetAsync(cntPtr, 0, (size_t)N * sizeof(int));

    histogram_kernel<<<(E + 511) / 512, 512>>>(dst, E);
    scan_kernel<<<1, 1024>>>(N);
    scatter_kernel<<<(E + 511) / 512, 512>>>(dst, E);
    sortwarp_kernel<<<(N * 32 + 255) / 256, 256>>>(src, N);

    if (forked) {
        cudaStreamWaitEvent(0, evJoin, 0);
    } else {
        qkv_gemm<<<ggrid, 256>>>(h, WQ, WK, WV, N);
    }

    aggregate_kernel<<<(N * 32 + 255) / 256, 256>>>(out, N);
}

// round 10
// speedup vs baseline: 1.0990x; 1.0990x over previous
#include <cuda_runtime.h>

#define IN_DIM 128
#define HD     128
#define MAXN   40000
#define MAXE   640000

typedef unsigned long long u64;

// Scratch (allocation-free: __device__ globals)
__device__ float g_Q[MAXN * HD];
__device__ float g_K[MAXN * HD];
__device__ float g_V[MAXN * HD];
__device__ int   g_cnt[MAXN];
__device__ int   g_rowptr[MAXN + 1];
__device__ int   g_cursor[MAXN];
__device__ int   g_eidx[MAXE];   // edge indices grouped by dst
__device__ int   g_srcs[MAXE];   // src[eidx] in ascending-edge order per dst

// Packed dual-FP32 FMA (Blackwell f32x2 pipe). Each half is an independent
// IEEE fp32 fma.rn — bit-identical to two scalar __fmaf_rn.
__device__ __forceinline__ u64 fma2(u64 a, u64 b, u64 c)
{
    u64 d;
    asm("fma.rn.f32x2 %0, %1, %2, %3;" : "=l"(d) : "l"(a), "l"(b), "l"(c));
    return d;
}
__device__ __forceinline__ u64 dup2(float x)
{
    u64 d;
    asm("mov.b64 %0, {%1, %1};" : "=l"(d) : "f"(x));
    return d;
}

// ---------------------------------------------------------------------------
// CSR build: histogram by dst (4 edges per thread for MLP)
// ---------------------------------------------------------------------------
__global__ void histogram_kernel(const int* __restrict__ dst, int E)
{
    int base = (blockIdx.x * blockDim.x + threadIdx.x) * 4;
    if (base + 4 <= E) {
        int4 d = *(const int4*)&dst[base];
        atomicAdd(&g_cnt[d.x], 1);
        atomicAdd(&g_cnt[d.y], 1);
        atomicAdd(&g_cnt[d.z], 1);
        atomicAdd(&g_cnt[d.w], 1);
    } else {
        for (int e = base; e < E; e++) atomicAdd(&g_cnt[dst[e]], 1);
    }
}

// Single-block exclusive scan over g_cnt -> g_rowptr / g_cursor
__global__ void scan_kernel(int n)
{
    __shared__ int sm[1024];
    const int t = threadIdx.x;
    const int chunk = (n + 1023) / 1024;
    int b = t * chunk;
    int e = b + chunk; if (e > n) e = n;
    if (b > n) b = n;

    int s = 0;
    for (int i = b; i < e; i++) s += g_cnt[i];
    sm[t] = s;
    __syncthreads();
    for (int off = 1; off < 1024; off <<= 1) {
        int x = (t >= off) ? sm[t - off] : 0;
        __syncthreads();
        sm[t] += x;
        __syncthreads();
    }
    int run = sm[t] - s;
    for (int i = b; i < e; i++) {
        g_rowptr[i] = run;
        g_cursor[i] = run;
        run += g_cnt[i];
    }
    if (t == 1023) g_rowptr[n] = sm[1023];
}

// Scatter EDGE INDICES, 4 per thread (intra-row order fixed by rank sort)
__global__ void scatter_kernel(const int* __restrict__ dst, int E)
{
    int base = (blockIdx.x * blockDim.x + threadIdx.x) * 4;
    if (base + 4 <= E) {
        int4 d = *(const int4*)&dst[base];
        int p0 = atomicAdd(&g_cursor[d.x], 1);
        int p1 = atomicAdd(&g_cursor[d.y], 1);
        int p2 = atomicAdd(&g_cursor[d.z], 1);
        int p3 = atomicAdd(&g_cursor[d.w], 1);
        g_eidx[p0] = base + 0;
        g_eidx[p1] = base + 1;
        g_eidx[p2] = base + 2;
        g_eidx[p3] = base + 3;
    } else {
        for (int e = base; e < E; e++) {
            int pos = atomicAdd(&g_cursor[dst[e]], 1);
            g_eidx[pos] = e;
        }
    }
}

// Warp-per-node rank sort. Edge indices are distinct: ascending position of
// x is |{y : y < x}|. d<=32: pure register/shfl path (no smem, no syncwarp).
__global__ __launch_bounds__(256) void sortwarp_kernel(const int* __restrict__ src, int n)
{
    __shared__ int buf[8][128];
    const int warp   = (blockIdx.x * blockDim.x + threadIdx.x) >> 5;
    const int wlocal = (threadIdx.x >> 5);
    const int lane   = threadIdx.x & 31;
    if (warp >= n) return;

    const int beg = g_rowptr[warp];
    const int end = g_rowptr[warp + 1];
    const int d   = end - beg;

    if (d <= 0) return;
    if (d == 1) {
        if (lane == 0) g_srcs[beg] = src[g_eidx[beg]];
        return;
    }
    if (d <= 32) {
        int e = (lane < d) ? g_eidx[beg + lane] : 0x7fffffff;
        int r = 0;
#pragma unroll
        for (int j = 0; j < 32; j++) {
            int x = __shfl_sync(0xffffffffu, e, j);
            r += (x < e);
        }
        if (lane < d) g_srcs[beg + r] = src[e];
        return;
    }
    if (d <= 128) {
        for (int i = lane; i < d; i += 32) buf[wlocal][i] = g_eidx[beg + i];
        __syncwarp();
        for (int i = lane; i < d; i += 32) {
            int e = buf[wlocal][i];
            int r = 0;
            for (int j = 0; j < d; j++) r += (buf[wlocal][j] < e);
            g_srcs[beg + r] = src[e];
        }
    } else if (lane == 0) {  // astronomically unlikely fallback
        for (int i = beg + 1; i < end; i++) {
            int key = g_eidx[i];
            int j = i - 1;
            while (j >= beg && g_eidx[j] > key) { g_eidx[j + 1] = g_eidx[j]; j--; }
            g_eidx[j + 1] = key;
        }
        for (int i = beg; i < end; i++) g_srcs[i] = src[g_eidx[i]];
    }
}

// ---------------------------------------------------------------------------
// QKV GEMM (fp32) — R8-measured-good version (exact revert of R9's v3).
// C = A[M x 128] * W[128 x 128]  (blockIdx.y: 0=Q, 1=K, 2=V)
// Per output element: one sequential fused-FMA chain over k = 0..127
// ascending (bit-exact vs reference), packed fma.rn.f32x2 over column pairs.
// 128x128 block tile, BK=8, 256 threads, 8 rows x 8 cols per thread.
// ---------------------------------------------------------------------------
__global__ __launch_bounds__(256) void qkv_gemm(
    const float* __restrict__ A,
    const float* __restrict__ WQ,
    const float* __restrict__ WK,
    const float* __restrict__ WV,
    int M)
{
    const float* W = (blockIdx.y == 0) ? WQ : (blockIdx.y == 1) ? WK : WV;
    float* C = (blockIdx.y == 0) ? g_Q : (blockIdx.y == 1) ? g_K : g_V;

    __shared__ float As[8][128];
    __shared__ float Bs[8][128];

    const int tid  = threadIdx.x;
    const int row0 = blockIdx.x * 128;

    const int tr = (tid >> 4) * 8;
    const int tc = (tid & 15) * 8;

    const int arow  = tid >> 1;
    const int akcol = (tid & 1) * 4;
    const int brow = tid >> 5;
    const int bcol = (tid & 31) * 4;

    // acc2[i][p] = packed (C[tr+i][tc+2p], C[tr+i][tc+2p+1])
    u64 acc2[8][4];
#pragma unroll
    for (int i = 0; i < 8; i++)
#pragma unroll
        for (int p = 0; p < 4; p++) acc2[i][p] = 0ULL;

    for (int kc = 0; kc < IN_DIM; kc += 8) {
        float4 av = make_float4(0.f, 0.f, 0.f, 0.f);
        if (row0 + arow < M)
            av = *(const float4*)&A[(row0 + arow) * IN_DIM + kc + akcol];
        As[akcol + 0][arow] = av.x;
        As[akcol + 1][arow] = av.y;
        As[akcol + 2][arow] = av.z;
        As[akcol + 3][arow] = av.w;

        float4 bv = *(const float4*)&W[(kc + brow) * HD + bcol];
        *(float4*)&Bs[brow][bcol] = bv;
        __syncthreads();

#pragma unroll
        for (int k = 0; k < 8; k++) {
            float a[8];
            *(float4*)&a[0] = *(const float4*)&As[k][tr];
            *(float4*)&a[4] = *(const float4*)&As[k][tr + 4];
            ulonglong2 bl = *(const ulonglong2*)&Bs[k][tc];
            ulonglong2 bh = *(const ulonglong2*)&Bs[k][tc + 4];
#pragma unroll
            for (int i = 0; i < 8; i++) {
                u64 ad = dup2(a[i]);
                acc2[i][0] = fma2(ad, bl.x, acc2[i][0]);
                acc2[i][1] = fma2(ad, bl.y, acc2[i][1]);
                acc2[i][2] = fma2(ad, bh.x, acc2[i][2]);
                acc2[i][3] = fma2(ad, bh.y, acc2[i][3]);
            }
        }
        __syncthreads();
    }

#pragma unroll
    for (int i = 0; i < 8; i++) {
        int r = row0 + tr + i;
        if (r < M) {
            *(ulonglong2*)&C[r * HD + tc]     = make_ulonglong2(acc2[i][0], acc2[i][1]);
            *(ulonglong2*)&C[r * HD + tc + 4] = make_ulonglong2(acc2[i][2], acc2[i][3]);
        }
    }
}

// ---------------------------------------------------------------------------
// Edge phase, bit-exact (ascending edge order per dst, per-channel chains):
//   score = (K[src]*Q[dst]) * 0.25f ; z += score ; wv += V[src]*score
//   out   = wv / (z + 1e-6f)
// v4: 64 threads per node, float2 (2 channels) per lane — doubles the warp
// count feeding the L2 (latency hiding) at identical byte traffic; the FP
// sequence per channel is unchanged. Unroll x4 keeps registers comfortable.
// ---------------------------------------------------------------------------
__device__ __forceinline__ void edge_step2(float2 k, float2 v, const float2& q,
                                           float2& z, float2& w)
{
    float sc0 = __fmul_rn(__fmul_rn(k.x, q.x), 0.25f);
    float sc1 = __fmul_rn(__fmul_rn(k.y, q.y), 0.25f);
    z.x = __fadd_rn(z.x, sc0);
    z.y = __fadd_rn(z.y, sc1);
    w.x = __fadd_rn(w.x, __fmul_rn(v.x, sc0));
    w.y = __fadd_rn(w.y, __fmul_rn(v.y, sc1));
}

__global__ __launch_bounds__(256) void aggregate_kernel(float* __restrict__ out, int n)
{
    int node = (blockIdx.x * blockDim.x + threadIdx.x) >> 6;
    if (node >= n) return;
    const int lane = threadIdx.x & 63;   // channel-pair index (2 ch per lane)

    const int beg = g_rowptr[node];
    const int end = g_rowptr[node + 1];

    const float2* __restrict__ K2 = (const float2*)g_K;
    const float2* __restrict__ V2 = (const float2*)g_V;

    float2 q = ((const float2*)g_Q)[node * 64 + lane];

    float2 z = make_float2(0.f, 0.f);
    float2 w = make_float2(0.f, 0.f);

    int j = beg;
    for (; j + 4 <= end; j += 4) {
        int s0 = g_srcs[j + 0];
        int s1 = g_srcs[j + 1];
        int s2 = g_srcs[j + 2];
        int s3 = g_srcs[j + 3];
        float2 k0 = K2[s0 * 64 + lane], v0 = V2[s0 * 64 + lane];
        float2 k1 = K2[s1 * 64 + lane], v1 = V2[s1 * 64 + lane];
        float2 k2 = K2[s2 * 64 + lane], v2 = V2[s2 * 64 + lane];
        float2 k3 = K2[s3 * 64 + lane], v3 = V2[s3 * 64 + lane];
        edge_step2(k0, v0, q, z, w);
        edge_step2(k1, v1, q, z, w);
        edge_step2(k2, v2, q, z, w);
        edge_step2(k3, v3, q, z, w);
    }
    for (; j < end; j++) {
        int s = g_srcs[j];
        edge_step2(K2[s * 64 + lane], V2[s * 64 + lane], q, z, w);
    }

    float2 r;
    r.x = __fdiv_rn(w.x, __fadd_rn(z.x, 1e-6f));
    r.y = __fdiv_rn(w.y, __fadd_rn(z.y, 1e-6f));

    ((float2*)out)[node * 64 + lane] = r;
}

// ---------------------------------------------------------------------------
// Launch: fork the (independent) QKV GEMM onto a second capture stream so the
// CSR-build chain overlaps it in the captured graph; join before aggregate.
// Streams/events are host objects (no device memory) created fresh per call.
// ---------------------------------------------------------------------------
extern "C" void kernel_launch(void* const* d_in, const int* in_sizes, int n_in,
                              void* d_out, int out_size)
{
    const float* h   = (const float*)d_in[0];
    const int*   src = (const int*)  d_in[1];
    const int*   dst = (const int*)  d_in[2];
    const float* WQ  = (const float*)d_in[3];
    const float* WK  = (const float*)d_in[4];
    const float* WV  = (const float*)d_in[5];
    float* out = (float*)d_out;

    const int N = in_sizes[0] / IN_DIM;
    const int E = in_sizes[1];

    // Try to set up a parallel branch for the GEMM
    cudaStream_t s2 = nullptr;
    cudaEvent_t evFork = nullptr, evJoin = nullptr;
    bool forked =
        (cudaStreamCreateWithFlags(&s2, cudaStreamNonBlocking) == cudaSuccess) &&
        (cudaEventCreateWithFlags(&evFork, cudaEventDisableTiming) == cudaSuccess) &&
        (cudaEventCreateWithFlags(&evJoin, cudaEventDisableTiming) == cudaSuccess);

    dim3 ggrid((N + 127) / 128, 3);

    if (forked) {
        forked = (cudaEventRecord(evFork, 0) == cudaSuccess) &&
                 (cudaStreamWaitEvent(s2, evFork, 0) == cudaSuccess);
    }
    if (forked) {
        qkv_gemm<<<ggrid, 256, 0, s2>>>(h, WQ, WK, WV, N);
        forked = (cudaEventRecord(evJoin, s2) == cudaSuccess);
    }

    // CSR-build chain on the main (captured) stream
    void* cntPtr = nullptr;
    cudaGetSymbolAddress(&cntPtr, g_cnt);
    cudaMemsetAsync(cntPtr, 0, (size_t)N * sizeof(int));

    const int eThreads = (E + 3) / 4;
    histogram_kernel<<<(eThreads + 511) / 512, 512>>>(dst, E);
    scan_kernel<<<1, 1024>>>(N);
    scatter_kernel<<<(eThreads + 511) / 512, 512>>>(dst, E);
    sortwarp_kernel<<<(N * 32 + 255) / 256, 256>>>(src, N);

    if (forked) {
        cudaStreamWaitEvent(0, evJoin, 0);
    } else {
        qkv_gemm<<<ggrid, 256>>>(h, WQ, WK, WV, N);
    }

    aggregate_kernel<<<(N * 64 + 255) / 256, 256>>>(out, N);
}

// round 11
// speedup vs baseline: 1.3247x; 1.2053x over previous
#include <cuda_runtime.h>

#define IN_DIM 128
#define HD     128
#define MAXN   40000
#define MAXE   640000

typedef unsigned long long u64;

// Scratch (allocation-free: __device__ globals)
__device__ float g_Q[MAXN * HD];
__device__ float g_K[MAXN * HD];
__device__ float g_V[MAXN * HD];
__device__ int   g_cnt[MAXN];
__device__ int   g_rowptr[MAXN + 1];
__device__ int   g_cursor[MAXN];
__device__ int   g_eidx[MAXE];
__device__ int   g_srcs[MAXE];

// Packed dual-FP32 FMA (Blackwell f32x2 pipe). Each half is an independent
// IEEE fp32 fma.rn — bit-identical to two scalar __fmaf_rn.
__device__ __forceinline__ u64 fma2(u64 a, u64 b, u64 c)
{
    u64 d;
    asm("fma.rn.f32x2 %0, %1, %2, %3;" : "=l"(d) : "l"(a), "l"(b), "l"(c));
    return d;
}
__device__ __forceinline__ u64 dup2(float x)
{
    u64 d;
    asm("mov.b64 %0, {%1, %1};" : "=l"(d) : "f"(x));
    return d;
}

// ---------------------------------------------------------------------------
// CSR build: histogram by dst (4 edges per thread for MLP)
// ---------------------------------------------------------------------------
__global__ void histogram_kernel(const int* __restrict__ dst, int E)
{
    int base = (blockIdx.x * blockDim.x + threadIdx.x) * 4;
    if (base + 4 <= E) {
        int4 d = *(const int4*)&dst[base];
        atomicAdd(&g_cnt[d.x], 1);
        atomicAdd(&g_cnt[d.y], 1);
        atomicAdd(&g_cnt[d.z], 1);
        atomicAdd(&g_cnt[d.w], 1);
    } else {
        for (int e = base; e < E; e++) atomicAdd(&g_cnt[dst[e]], 1);
    }
}

__global__ void scan_kernel(int n)
{
    __shared__ int sm[1024];
    const int t = threadIdx.x;
    const int chunk = (n + 1023) / 1024;
    int b = t * chunk;
    int e = b + chunk; if (e > n) e = n;
    if (b > n) b = n;

    int s = 0;
    for (int i = b; i < e; i++) s += g_cnt[i];
    sm[t] = s;
    __syncthreads();
    for (int off = 1; off < 1024; off <<= 1) {
        int x = (t >= off) ? sm[t - off] : 0;
        __syncthreads();
        sm[t] += x;
        __syncthreads();
    }
    int run = sm[t] - s;
    for (int i = b; i < e; i++) {
        g_rowptr[i] = run;
        g_cursor[i] = run;
        run += g_cnt[i];
    }
    if (t == 1023) g_rowptr[n] = sm[1023];
}

__global__ void scatter_kernel(const int* __restrict__ dst, int E)
{
    int base = (blockIdx.x * blockDim.x + threadIdx.x) * 4;
    if (base + 4 <= E) {
        int4 d = *(const int4*)&dst[base];
        int p0 = atomicAdd(&g_cursor[d.x], 1);
        int p1 = atomicAdd(&g_cursor[d.y], 1);
        int p2 = atomicAdd(&g_cursor[d.z], 1);
        int p3 = atomicAdd(&g_cursor[d.w], 1);
        g_eidx[p0] = base + 0;
        g_eidx[p1] = base + 1;
        g_eidx[p2] = base + 2;
        g_eidx[p3] = base + 3;
    } else {
        for (int e = base; e < E; e++) {
            int pos = atomicAdd(&g_cursor[dst[e]], 1);
            g_eidx[pos] = e;
        }
    }
}

// Warp-per-node rank sort (ascending edge index = reference sum order)
__global__ __launch_bounds__(256) void sortwarp_kernel(const int* __restrict__ src, int n)
{
    __shared__ int buf[8][128];
    const int warp   = (blockIdx.x * blockDim.x + threadIdx.x) >> 5;
    const int wlocal = (threadIdx.x >> 5);
    const int lane   = threadIdx.x & 31;
    if (warp >= n) return;

    const int beg = g_rowptr[warp];
    const int end = g_rowptr[warp + 1];
    const int d   = end - beg;

    if (d <= 0) return;
    if (d == 1) {
        if (lane == 0) g_srcs[beg] = src[g_eidx[beg]];
        return;
    }
    if (d <= 32) {
        int e = (lane < d) ? g_eidx[beg + lane] : 0x7fffffff;
        int r = 0;
#pragma unroll
        for (int j = 0; j < 32; j++) {
            int x = __shfl_sync(0xffffffffu, e, j);
            r += (x < e);
        }
        if (lane < d) g_srcs[beg + r] = src[e];
        return;
    }
    if (d <= 128) {
        for (int i = lane; i < d; i += 32) buf[wlocal][i] = g_eidx[beg + i];
        __syncwarp();
        for (int i = lane; i < d; i += 32) {
            int e = buf[wlocal][i];
            int r = 0;
            for (int j = 0; j < d; j++) r += (buf[wlocal][j] < e);
            g_srcs[beg + r] = src[e];
        }
    } else if (lane == 0) {
        for (int i = beg + 1; i < end; i++) {
            int key = g_eidx[i];
            int j = i - 1;
            while (j >= beg && g_eidx[j] > key) { g_eidx[j + 1] = g_eidx[j]; j--; }
            g_eidx[j + 1] = key;
        }
        for (int i = beg; i < end; i++) g_srcs[i] = src[g_eidx[i]];
    }
}

// ---------------------------------------------------------------------------
// Half-column QKV GEMM: computes C[:, 64h .. 64h+63] for Q, K, V.
// Same measured-good inner loop as R8 (8x8 thread tile, BK=8, fma.rn.f32x2,
// k-ascending chain per element — bit-exact), block = 128 threads -> 128x64.
// grid = (ceil(M/128), 3);  h = column half (0 or 1).
// ---------------------------------------------------------------------------
__global__ __launch_bounds__(128) void qkv_gemm_half(
    const float* __restrict__ A,
    const float* __restrict__ WQ,
    const float* __restrict__ WK,
    const float* __restrict__ WV,
    int M, int h)
{
    const float* W = (blockIdx.y == 0) ? WQ : (blockIdx.y == 1) ? WK : WV;
    float* C = (blockIdx.y == 0) ? g_Q : (blockIdx.y == 1) ? g_K : g_V;
    const int col0 = h * 64;

    __shared__ float As[8][128];   // [k][m]
    __shared__ float Bs[8][64];    // [k][n-half]

    const int tid  = threadIdx.x;   // 0..127
    const int row0 = blockIdx.x * 128;

    const int tr = (tid >> 3) * 8;     // 16 row-groups of 8
    const int tc = (tid & 7) * 8;      // 8 col-groups of 8

    const int arow = tid;              // one row per thread, 8 k-values
    const int brow = tid >> 4;         // 0..7
    const int bcol = (tid & 15) * 4;   // 0..60

    u64 acc2[8][4];
#pragma unroll
    for (int i = 0; i < 8; i++)
#pragma unroll
        for (int p = 0; p < 4; p++) acc2[i][p] = 0ULL;

    const bool arow_ok = (row0 + arow < M);

    for (int kc = 0; kc < IN_DIM; kc += 8) {
        float4 av0 = make_float4(0.f, 0.f, 0.f, 0.f);
        float4 av1 = make_float4(0.f, 0.f, 0.f, 0.f);
        if (arow_ok) {
            av0 = *(const float4*)&A[(row0 + arow) * IN_DIM + kc];
            av1 = *(const float4*)&A[(row0 + arow) * IN_DIM + kc + 4];
        }
        As[0][arow] = av0.x;
        As[1][arow] = av0.y;
        As[2][arow] = av0.z;
        As[3][arow] = av0.w;
        As[4][arow] = av1.x;
        As[5][arow] = av1.y;
        As[6][arow] = av1.z;
        As[7][arow] = av1.w;

        *(float4*)&Bs[brow][bcol] =
            *(const float4*)&W[(kc + brow) * HD + col0 + bcol];
        __syncthreads();

#pragma unroll
        for (int k = 0; k < 8; k++) {
            float a[8];
            *(float4*)&a[0] = *(const float4*)&As[k][tr];
            *(float4*)&a[4] = *(const float4*)&As[k][tr + 4];
            ulonglong2 bl = *(const ulonglong2*)&Bs[k][tc];
            ulonglong2 bh = *(const ulonglong2*)&Bs[k][tc + 4];
#pragma unroll
            for (int i = 0; i < 8; i++) {
                u64 ad = dup2(a[i]);
                acc2[i][0] = fma2(ad, bl.x, acc2[i][0]);
                acc2[i][1] = fma2(ad, bl.y, acc2[i][1]);
                acc2[i][2] = fma2(ad, bh.x, acc2[i][2]);
                acc2[i][3] = fma2(ad, bh.y, acc2[i][3]);
            }
        }
        __syncthreads();
    }

#pragma unroll
    for (int i = 0; i < 8; i++) {
        int r = row0 + tr + i;
        if (r < M) {
            *(ulonglong2*)&C[r * HD + col0 + tc] =
                make_ulonglong2(acc2[i][0], acc2[i][1]);
            *(ulonglong2*)&C[r * HD + col0 + tc + 4] =
                make_ulonglong2(acc2[i][2], acc2[i][3]);
        }
    }
}

// ---------------------------------------------------------------------------
// Half-channel edge aggregate (bit-exact ascending edge order per channel):
//   score = (K*Q)*0.25f ; z += score ; wv += V*score ; out = wv/(z+1e-6f)
// One warp per node, channels [64h, 64h+64): float2 per lane.
// ---------------------------------------------------------------------------
__device__ __forceinline__ void edge_step2(float2 k, float2 v, const float2& q,
                                           float2& z, float2& w)
{
    float sc0 = __fmul_rn(__fmul_rn(k.x, q.x), 0.25f);
    float sc1 = __fmul_rn(__fmul_rn(k.y, q.y), 0.25f);
    z.x = __fadd_rn(z.x, sc0);
    z.y = __fadd_rn(z.y, sc1);
    w.x = __fadd_rn(w.x, __fmul_rn(v.x, sc0));
    w.y = __fadd_rn(w.y, __fmul_rn(v.y, sc1));
}

__global__ __launch_bounds__(256) void aggregate_half(float* __restrict__ out,
                                                      int n, int h)
{
    int node = (blockIdx.x * blockDim.x + threadIdx.x) >> 5;
    if (node >= n) return;
    const int lane = threadIdx.x & 31;
    const int ch   = h * 32 + lane;     // float2 index within the 64-pair row

    const int beg = g_rowptr[node];
    const int end = g_rowptr[node + 1];

    const float2* __restrict__ K2 = (const float2*)g_K;
    const float2* __restrict__ V2 = (const float2*)g_V;

    float2 q = ((const float2*)g_Q)[node * 64 + ch];

    float2 z = make_float2(0.f, 0.f);
    float2 w = make_float2(0.f, 0.f);

    int j = beg;
    for (; j + 4 <= end; j += 4) {
        int s0 = g_srcs[j + 0];
        int s1 = g_srcs[j + 1];
        int s2 = g_srcs[j + 2];
        int s3 = g_srcs[j + 3];
        float2 k0 = K2[s0 * 64 + ch], v0 = V2[s0 * 64 + ch];
        float2 k1 = K2[s1 * 64 + ch], v1 = V2[s1 * 64 + ch];
        float2 k2 = K2[s2 * 64 + ch], v2 = V2[s2 * 64 + ch];
        float2 k3 = K2[s3 * 64 + ch], v3 = V2[s3 * 64 + ch];
        edge_step2(k0, v0, q, z, w);
        edge_step2(k1, v1, q, z, w);
        edge_step2(k2, v2, q, z, w);
        edge_step2(k3, v3, q, z, w);
    }
    for (; j < end; j++) {
        int s = g_srcs[j];
        edge_step2(K2[s * 64 + ch], V2[s * 64 + ch], q, z, w);
    }

    float2 r;
    r.x = __fdiv_rn(w.x, __fadd_rn(z.x, 1e-6f));
    r.y = __fdiv_rn(w.y, __fadd_rn(z.y, 1e-6f));

    ((float2*)out)[node * 64 + ch] = r;
}

// ---------------------------------------------------------------------------
// Launch: channel-pipelined graph.
//   s2:   GEMM[cols 0-63] -evG0-> GEMM[cols 64-127] -evG1->
//   main: CSR chain ... wait(evG0) AGG[0-63] wait(evG1) AGG[64-127]
// AGG half 0 (L2-BW-bound) overlaps GEMM half 1 (FFMA-bound).
// ---------------------------------------------------------------------------
extern "C" void kernel_launch(void* const* d_in, const int* in_sizes, int n_in,
                              void* d_out, int out_size)
{
    const float* h   = (const float*)d_in[0];
    const int*   src = (const int*)  d_in[1];
    const int*   dst = (const int*)  d_in[2];
    const float* WQ  = (const float*)d_in[3];
    const float* WK  = (const float*)d_in[4];
    const float* WV  = (const float*)d_in[5];
    float* out = (float*)d_out;

    const int N = in_sizes[0] / IN_DIM;
    const int E = in_sizes[1];

    cudaStream_t s2 = nullptr;
    cudaEvent_t evG0 = nullptr, evG1 = nullptr, evFork = nullptr;
    bool forked =
        (cudaStreamCreateWithFlags(&s2, cudaStreamNonBlocking) == cudaSuccess) &&
        (cudaEventCreateWithFlags(&evFork, cudaEventDisableTiming) == cudaSuccess) &&
        (cudaEventCreateWithFlags(&evG0, cudaEventDisableTiming) == cudaSuccess) &&
        (cudaEventCreateWithFlags(&evG1, cudaEventDisableTiming) == cudaSuccess);

    dim3 ggrid((N + 127) / 128, 3);
    const int aggBlocks = (N * 32 + 255) / 256;

    if (forked) {
        forked = (cudaEventRecord(evFork, 0) == cudaSuccess) &&
                 (cudaStreamWaitEvent(s2, evFork, 0) == cudaSuccess);
    }
    if (forked) {
        qkv_gemm_half<<<ggrid, 128, 0, s2>>>(h, WQ, WK, WV, N, 0);
        forked = (cudaEventRecord(evG0, s2) == cudaSuccess);
        if (forked) {
            qkv_gemm_half<<<ggrid, 128, 0, s2>>>(h, WQ, WK, WV, N, 1);
            forked = (cudaEventRecord(evG1, s2) == cudaSuccess);
        }
    }

    // CSR-build chain on the main (captured) stream
    void* cntPtr = nullptr;
    cudaGetSymbolAddress(&cntPtr, g_cnt);
    cudaMemsetAsync(cntPtr, 0, (size_t)N * sizeof(int));

    const int eThreads = (E + 3) / 4;
    histogram_kernel<<<(eThreads + 511) / 512, 512>>>(dst, E);
    scan_kernel<<<1, 1024>>>(N);
    scatter_kernel<<<(eThreads + 511) / 512, 512>>>(dst, E);
    sortwarp_kernel<<<(N * 32 + 255) / 256, 256>>>(src, N);

    if (forked) {
        cudaStreamWaitEvent(0, evG0, 0);
        aggregate_half<<<aggBlocks, 256>>>(out, N, 0);
        cudaStreamWaitEvent(0, evG1, 0);
        aggregate_half<<<aggBlocks, 256>>>(out, N, 1);
    } else {
        // Serial fallback
        qkv_gemm_half<<<ggrid, 128>>>(h, WQ, WK, WV, N, 0);
        qkv_gemm_half<<<ggrid, 128>>>(h, WQ, WK, WV, N, 1);
        aggregate_half<<<aggBlocks, 256>>>(out, N, 0);
        aggregate_half<<<aggBlocks, 256>>>(out, N, 1);
    }
}